// round 4
// baseline (speedup 1.0000x reference)
#include <cuda_runtime.h>

// DeformationPerturbationLayer == bilinear sampling (zero-padded) of the image
// at src = pixel + w[b] * bulge_displacement(pixel).
//
// image: [C=3, H=64, W=64] fp32
// w:     [B=8, 1] fp32
// out:   [B=8, C=3, H=64, W=64] fp32
//
// R4: float4-vectorized — each thread produces 4 x-adjacent pixels of one
// (b, c, row) and writes a single STG.128. 24576 threads = 192 CTAs x 128.
// Cuts dynamic instructions per output ~2x and stores 4x; 16 gathers per
// thread hit mostly-adjacent sectors (good L1 wavefront packing).

#define B_ 8
#define C_ 3
#define H_ 64
#define W_ 64
#define NPIX (H_ * W_)

__global__ __launch_bounds__(128, 8)
void deform_kernel(const float* __restrict__ w,
                   const float* __restrict__ img,
                   float4* __restrict__ out4)
{
    int idx = blockIdx.x * blockDim.x + threadIdx.x;   // 0 .. 24575, grid exact

    // idx -> (plane, y, x-group of 4); out4[idx] is exactly this quad.
    int xg    = (idx & 15) << 2;          // x base: 0,4,...,60
    int y     = (idx >> 4) & 63;
    int plane = idx >> 10;                // b*3 + c, 0..23
    int b     = plane / 3;                // const-div -> mul.hi
    int c     = plane - b * 3;

    float wb = __ldg(w + b);
    const float* ic = img + c * NPIX;

    const float cx = (W_ - 1) * 0.5f;     // 31.5
    const float cy = (H_ - 1) * 0.5f;
    const float inv_two_sigma2 = 1.0f / 512.0f;   // sigma = 16

    float fyp = __int2float_rn(y);
    float dyc = cy - fyp;
    float dyc2 = dyc * dyc;

    float res[4];

#pragma unroll
    for (int j = 0; j < 4; ++j) {
        int x = xg + j;
        float fxp = __int2float_rn(x);
        float dxc = cx - fxp;
        float r2  = fmaf(dxc, dxc, dyc2);
        float g   = __expf(-r2 * inv_two_sigma2);    // FMUL + MUFU.EX2
        float wg  = wb * g;

        float sx = fmaf(wg, dxc, fxp);
        float sy = fmaf(wg, dyc, fyp);

        int x0 = __float2int_rd(sx);
        int y0 = __float2int_rd(sy);
        float tx = sx - __int2float_rn(x0);
        float ty = sy - __int2float_rn(y0);

        float wx0 = 1.0f - tx, wx1 = tx;
        float wy0 = 1.0f - ty, wy1 = ty;

        int x1 = x0 + 1, y1 = y0 + 1;
        if ((unsigned)x0 >= W_) wx0 = 0.0f;
        if ((unsigned)x1 >= W_) wx1 = 0.0f;
        if ((unsigned)y0 >= H_) wy0 = 0.0f;
        if ((unsigned)y1 >= H_) wy1 = 0.0f;

        int cx0 = min(max(x0, 0), W_ - 1);
        int cx1 = min(max(x1, 0), W_ - 1);
        int cy0 = min(max(y0, 0), H_ - 1);
        int cy1 = min(max(y1, 0), H_ - 1);

        float w00 = wy0 * wx0;
        float w01 = wy0 * wx1;
        float w10 = wy1 * wx0;
        float w11 = wy1 * wx1;

        int r0 = cy0 << 6;
        int r1 = cy1 << 6;

        float v00 = __ldg(ic + r0 + cx0);
        float v01 = __ldg(ic + r0 + cx1);
        float v10 = __ldg(ic + r1 + cx0);
        float v11 = __ldg(ic + r1 + cx1);

        res[j] = fmaf(w00, v00, w01 * v01) + fmaf(w10, v10, w11 * v11);
    }

    out4[idx] = make_float4(res[0], res[1], res[2], res[3]);
}

extern "C" void kernel_launch(void* const* d_in, const int* in_sizes, int n_in,
                              void* d_out, int out_size)
{
    const float* w   = (const float*)d_in[0];   // [8,1]
    const float* img = (const float*)d_in[1];   // [3,64,64]
    float4* out4 = (float4*)d_out;              // [8,3,64,64] as quads

    const int threads = (B_ * C_ * NPIX) / 4;   // 24576
    deform_kernel<<<threads / 128, 128>>>(w, img, out4);
}

// round 5
// speedup vs baseline: 1.0047x; 1.0047x over previous
#include <cuda_runtime.h>

// DeformationPerturbationLayer == bilinear sampling of the image at
// src = pixel + w[b] * bulge_displacement(pixel).
//
// Key algebraic fact: src = x + w*(center-x)*g with w in [0,1), g in (0,1]
// is a convex combination of x and the center, so src is ALWAYS in [0, 63].
// The reference's zero-padding boundary handling is dead code -> no weight
// zeroing, no lower clamps. Only min(x1,63)/min(y1,63) retained for the
// exact-63.0 edge (its weight is 0; clamp just keeps the load in-bounds).
//
// image: [C=3, H=64, W=64] fp32
// w:     [B=8, 1] fp32
// out:   [B=8, C=3, H=64, W=64] fp32
//
// R5: R2 layout (best kernel dur) — one thread per (b, pixel), 3 channels,
// 12 independent gathers (MLP=12) — with boundary math eliminated.

#define B_ 8
#define C_ 3
#define H_ 64
#define W_ 64
#define NPIX (H_ * W_)

__global__ __launch_bounds__(256, 8)
void deform_kernel(const float* __restrict__ w,
                   const float* __restrict__ img,
                   float* __restrict__ out)
{
    int idx = blockIdx.x * blockDim.x + threadIdx.x;   // 0 .. 32767, grid exact

    int b   = idx >> 12;          // / 4096
    int pix = idx & (NPIX - 1);   // % 4096
    int y   = pix >> 6;
    int x   = pix & 63;

    float wb = __ldg(w + b);

    const float cx = (W_ - 1) * 0.5f;   // 31.5
    const float cy = (H_ - 1) * 0.5f;
    float fxp = __int2float_rn(x);
    float fyp = __int2float_rn(y);
    float dxc = cx - fxp;
    float dyc = cy - fyp;
    const float inv_two_sigma2 = 1.0f / 512.0f;        // sigma = 16
    float r2 = fmaf(dxc, dxc, dyc * dyc);
    float g  = __expf(-r2 * inv_two_sigma2);           // FMUL + MUFU.EX2
    float wg = wb * g;

    float sx = fmaf(wg, dxc, fxp);     // in [0, 63] by convexity
    float sy = fmaf(wg, dyc, fyp);

    int x0 = __float2int_rd(sx);       // in [0, 63]
    int y0 = __float2int_rd(sy);
    float tx = sx - __int2float_rn(x0);
    float ty = sy - __int2float_rn(y0);

    int x1 = min(x0 + 1, W_ - 1);      // only differs from x0+1 when tx == 0
    int y1 = min(y0 + 1, H_ - 1);

    float w11 = ty * tx;
    float w10 = ty - w11;              // ty * (1 - tx)
    float w01 = tx - w11;              // (1 - ty) * tx
    float w00 = 1.0f - ty - w01;       // (1 - ty) * (1 - tx)

    int r0 = y0 << 6;
    int r1 = y1 << 6;
    int i00 = r0 + x0;
    int i01 = r0 + x1;
    int i10 = r1 + x0;
    int i11 = r1 + x1;

    float* ob = out + b * (C_ * NPIX) + pix;

#pragma unroll
    for (int c = 0; c < C_; ++c) {
        const float* ic = img + c * NPIX;
        float v00 = __ldg(ic + i00);
        float v01 = __ldg(ic + i01);
        float v10 = __ldg(ic + i10);
        float v11 = __ldg(ic + i11);
        float v = fmaf(w00, v00, w01 * v01) + fmaf(w10, v10, w11 * v11);
        ob[c * NPIX] = v;
    }
}

extern "C" void kernel_launch(void* const* d_in, const int* in_sizes, int n_in,
                              void* d_out, int out_size)
{
    const float* w   = (const float*)d_in[0];   // [8,1]
    const float* img = (const float*)d_in[1];   // [3,64,64]
    float* out = (float*)d_out;                 // [8,3,64,64]

    deform_kernel<<<(B_ * NPIX) / 256, 256>>>(w, img, out);
}

// round 6
// speedup vs baseline: 1.0385x; 1.0337x over previous
#include <cuda_runtime.h>

// DeformationPerturbationLayer == bilinear sampling of the image at
// src = pixel + w[b] * bulge_displacement(pixel).
//
// Algebraic fact: src = x + w*(center-x)*g, w in [0,1), g in (0,1] is a
// convex combination of x and the center => src in [0,63] always. The
// reference's zero-padding boundary handling is dead code; only the
// min(+1, 63) upper clamp survives (weight 0 there, keeps loads in-bounds).
//
// image: [C=3, H=64, W=64] fp32
// w:     [B=8, 1] fp32
// out:   [B=8, C=3, H=64, W=64] fp32
//
// R6: ramp shaping. Same 32768 threads as the best variant, but 256 CTAs
// x 128 threads so wave 1 covers all 148 SMs (vs 128) with finer drain
// granularity. Kernel is launch-ramp + single-DRAM-round-trip bound
// (all pipes <2%); instruction count is off the critical path.

#define B_ 8
#define C_ 3
#define H_ 64
#define W_ 64
#define NPIX (H_ * W_)

__global__ __launch_bounds__(128, 16)
void deform_kernel(const float* __restrict__ w,
                   const float* __restrict__ img,
                   float* __restrict__ out)
{
    int idx = blockIdx.x * blockDim.x + threadIdx.x;   // 0 .. 32767, grid exact

    int b   = idx >> 12;          // / 4096
    int pix = idx & (NPIX - 1);   // % 4096
    int y   = pix >> 6;
    int x   = pix & 63;

    float wb = __ldg(w + b);      // issue immediately

    const float cx = (W_ - 1) * 0.5f;   // 31.5
    const float cy = (H_ - 1) * 0.5f;
    float fxp = __int2float_rn(x);
    float fyp = __int2float_rn(y);
    float dxc = cx - fxp;
    float dyc = cy - fyp;
    const float inv_two_sigma2 = 1.0f / 512.0f;        // sigma = 16
    float r2 = fmaf(dxc, dxc, dyc * dyc);
    float g  = __expf(-r2 * inv_two_sigma2);           // FMUL + MUFU.EX2
    float wg = wb * g;

    float sx = fmaf(wg, dxc, fxp);     // in [0, 63] by convexity
    float sy = fmaf(wg, dyc, fyp);

    int x0 = __float2int_rd(sx);       // in [0, 63]
    int y0 = __float2int_rd(sy);
    float tx = sx - __int2float_rn(x0);
    float ty = sy - __int2float_rn(y0);

    int x1 = min(x0 + 1, W_ - 1);      // differs from x0+1 only when tx == 0
    int y1 = min(y0 + 1, H_ - 1);

    int r0 = y0 << 6;
    int r1 = y1 << 6;
    int i00 = r0 + x0;
    int i01 = r0 + x1;
    int i10 = r1 + x0;
    int i11 = r1 + x1;

    // issue all 12 gathers before the weight math finishes (independent)
    float v00a = __ldg(img + i00);
    float v01a = __ldg(img + i01);
    float v10a = __ldg(img + i10);
    float v11a = __ldg(img + i11);
    float v00b = __ldg(img + NPIX + i00);
    float v01b = __ldg(img + NPIX + i01);
    float v10b = __ldg(img + NPIX + i10);
    float v11b = __ldg(img + NPIX + i11);
    float v00c = __ldg(img + 2 * NPIX + i00);
    float v01c = __ldg(img + 2 * NPIX + i01);
    float v10c = __ldg(img + 2 * NPIX + i10);
    float v11c = __ldg(img + 2 * NPIX + i11);

    float w11 = ty * tx;
    float w10 = ty - w11;              // ty * (1 - tx)
    float w01 = tx - w11;              // (1 - ty) * tx
    float w00 = 1.0f - ty - w01;       // (1 - ty) * (1 - tx)

    float* ob = out + b * (C_ * NPIX) + pix;
    ob[0]        = fmaf(w00, v00a, w01 * v01a) + fmaf(w10, v10a, w11 * v11a);
    ob[NPIX]     = fmaf(w00, v00b, w01 * v01b) + fmaf(w10, v10b, w11 * v11b);
    ob[2 * NPIX] = fmaf(w00, v00c, w01 * v01c) + fmaf(w10, v10c, w11 * v11c);
}

extern "C" void kernel_launch(void* const* d_in, const int* in_sizes, int n_in,
                              void* d_out, int out_size)
{
    const float* w   = (const float*)d_in[0];   // [8,1]
    const float* img = (const float*)d_in[1];   // [3,64,64]
    float* out = (float*)d_out;                 // [8,3,64,64]

    deform_kernel<<<(B_ * NPIX) / 128, 128>>>(w, img, out);
}

// round 7
// speedup vs baseline: 1.0435x; 1.0048x over previous
#include <cuda_runtime.h>

// DeformationPerturbationLayer == bilinear sampling of the image at
// src = pixel + w[b] * bulge_displacement(pixel).
//
// Algebraic fact: src = x + w*(center-x)*g with w in [0,1), g in (0,1] is a
// convex combination of x and the image center => src in [0,63] always.
// The reference's zero-padding boundary handling is provably dead code;
// only the min(+1, 63) upper clamp survives (its tap weight is exactly 0,
// the clamp merely keeps the load in-bounds).
//
// image: [C=3, H=64, W=64] fp32
// w:     [B=8, 1] fp32
// out:   [B=8, C=3, H=64, W=64] fp32
//
// R7 (final synthesis): empirically-best launch shape of the session
// (grid 128 x 256 threads, one thread per (b,pixel), 3 channels/thread,
// kernel 4.32us in R2) + convexity-eliminated boundary math + all 12
// independent gathers issued before the weight arithmetic (MLP=12).
// Session evidence: kernel is launch-ramp bound (all pipes <2%, DRAM 0.1%);
// wall floor ~6.5us = T_ovh + one L2 round-trip + graph-replay overhead.

#define B_ 8
#define C_ 3
#define H_ 64
#define W_ 64
#define NPIX (H_ * W_)

__global__ __launch_bounds__(256, 8)
void deform_kernel(const float* __restrict__ w,
                   const float* __restrict__ img,
                   float* __restrict__ out)
{
    int idx = blockIdx.x * blockDim.x + threadIdx.x;   // 0 .. 32767, grid exact

    int b   = idx >> 12;          // / 4096
    int pix = idx & (NPIX - 1);   // % 4096
    int y   = pix >> 6;
    int x   = pix & 63;

    float wb = __ldg(w + b);      // broadcast load, issued first

    const float cx = (W_ - 1) * 0.5f;   // 31.5
    const float cy = (H_ - 1) * 0.5f;
    float fxp = __int2float_rn(x);
    float fyp = __int2float_rn(y);
    float dxc = cx - fxp;
    float dyc = cy - fyp;
    const float inv_two_sigma2 = 1.0f / 512.0f;        // sigma = 16
    float r2 = fmaf(dxc, dxc, dyc * dyc);
    float g  = __expf(-r2 * inv_two_sigma2);           // FMUL + MUFU.EX2
    float wg = wb * g;

    float sx = fmaf(wg, dxc, fxp);     // in [0, 63] by convexity
    float sy = fmaf(wg, dyc, fyp);

    int x0 = __float2int_rd(sx);       // in [0, 63]
    int y0 = __float2int_rd(sy);
    float tx = sx - __int2float_rn(x0);
    float ty = sy - __int2float_rn(y0);

    int x1 = min(x0 + 1, W_ - 1);      // differs from x0+1 only when tx == 0
    int y1 = min(y0 + 1, H_ - 1);

    int r0 = y0 << 6;
    int r1 = y1 << 6;
    int i00 = r0 + x0;
    int i01 = r0 + x1;
    int i10 = r1 + x0;
    int i11 = r1 + x1;

    // all 12 gathers are independent — issue before the weight math
    float v00a = __ldg(img + i00);
    float v01a = __ldg(img + i01);
    float v10a = __ldg(img + i10);
    float v11a = __ldg(img + i11);
    float v00b = __ldg(img + NPIX + i00);
    float v01b = __ldg(img + NPIX + i01);
    float v10b = __ldg(img + NPIX + i10);
    float v11b = __ldg(img + NPIX + i11);
    float v00c = __ldg(img + 2 * NPIX + i00);
    float v01c = __ldg(img + 2 * NPIX + i01);
    float v10c = __ldg(img + 2 * NPIX + i10);
    float v11c = __ldg(img + 2 * NPIX + i11);

    float w11 = ty * tx;
    float w10 = ty - w11;              // ty * (1 - tx)
    float w01 = tx - w11;              // (1 - ty) * tx
    float w00 = 1.0f - ty - w01;       // (1 - ty) * (1 - tx)

    float* ob = out + b * (C_ * NPIX) + pix;
    ob[0]        = fmaf(w00, v00a, w01 * v01a) + fmaf(w10, v10a, w11 * v11a);
    ob[NPIX]     = fmaf(w00, v00b, w01 * v01b) + fmaf(w10, v10b, w11 * v11b);
    ob[2 * NPIX] = fmaf(w00, v00c, w01 * v01c) + fmaf(w10, v10c, w11 * v11c);
}

extern "C" void kernel_launch(void* const* d_in, const int* in_sizes, int n_in,
                              void* d_out, int out_size)
{
    const float* w   = (const float*)d_in[0];   // [8,1]
    const float* img = (const float*)d_in[1];   // [3,64,64]
    float* out = (float*)d_out;                 // [8,3,64,64]

    deform_kernel<<<(B_ * NPIX) / 256, 256>>>(w, img, out);
}